// round 12
// baseline (speedup 1.0000x reference)
#include <cuda_runtime.h>
#include <cuda_bf16.h>

// out[i] = input[segm_img[i]] : 1024-entry fp32 LUT gather over a 4096x4096
// index image. DRAM floor: 64MB idx read + 64MB out write ~= 19.7us @6.5TB/s.
//
// R9 evidence: kernel 21.1us (~93% of floor), L1tex hottest pipe (59%),
// dominated by 32->32-bank conflicted LDS gathers (E[max]~3.9 phases).
// This round: 8-way BANK-SLICED LUT replication (32KB smem). Replica r lives
// only in banks 4r..4r+3; lane l reads replica l>>2, so conflicts are
// 4-into-4 (E[max]~1.9, warp phases ~2.3) -> ~40% fewer LDS wavefronts.
//
// Dtype probe (per-CTA, 1KB, L2-hot): int64 values in [0,1024) have all-zero
// odd 32-bit words; random int32 indices OR to nonzero w.p. 1 - 1024^-128.

#define N_SEGM  1024
#define THREADS 256
#define GPI     2                 // 16B-index groups per thread per iteration
#define MAX_BLOCKS 888            // 148 SMs * 6 CTAs -> one wave
#define LUT_WORDS (N_SEGM * 8)    // 8 replicas, bank-sliced, 32 KB

// word address of LUT entry idx for a lane with replica-offset roff (= lane & 0x1C)
__device__ __forceinline__ int lut_word(int idx, int roff) {
    return ((idx & ~3) << 3) + roff + (idx & 3);
}

__global__ __launch_bounds__(THREADS, 6)
void superpixel2pixel_kernel(const float* __restrict__ lut_g,
                             const void*  __restrict__ segm,
                             float*       __restrict__ out,
                             int n4)   // number of 4-pixel groups
{
    __shared__ float lut[LUT_WORDS];
    __shared__ unsigned int probe_acc;

    if (threadIdx.x == 0) probe_acc = 0u;
    __syncthreads();

    if (threadIdx.x < 64) {
        uint4 w = reinterpret_cast<const uint4*>(segm)[threadIdx.x];
        unsigned int v = w.y | w.w;            // odd 32-bit words
        if (v) atomicOr(&probe_acc, v);
    }
    // Bank-sliced replicated LUT init: slot s -> row=s>>5, replica=(s>>2)&7,
    // col=s&3, entry = ((s>>5)<<2) | (s&3). Reads hit L1/L2 (4KB source).
    for (int s = threadIdx.x; s < LUT_WORDS; s += THREADS)
        lut[s] = lut_g[((s >> 5) << 2) | (s & 3)];
    __syncthreads();

    const bool is64   = (probe_acc == 0u);     // uniform
    const int  stride = gridDim.x * THREADS * GPI;
    const int  roff   = threadIdx.x & 0x1C;    // 4*(lane>>2), lane-local replica

    if (!is64) {
        const int4* sp = (const int4*)segm;
        int base = blockIdx.x * THREADS * GPI + threadIdx.x;

        // prologue: prefetch iteration 0
        int4 v[GPI];
        #pragma unroll
        for (int k = 0; k < GPI; k++) {
            int i = base + k * THREADS;
            if (i < n4) v[k] = __ldcs(sp + i);
        }

        while (base < n4) {
            int next = base + stride;
            int4 nv[GPI];
            #pragma unroll
            for (int k = 0; k < GPI; k++) {
                int i = next + k * THREADS;
                if (i < n4) nv[k] = __ldcs(sp + i);
            }
            #pragma unroll
            for (int k = 0; k < GPI; k++) {
                int i = base + k * THREADS;
                if (i < n4) {
                    float4 o;
                    o.x = lut[lut_word(v[k].x & (N_SEGM - 1), roff)];
                    o.y = lut[lut_word(v[k].y & (N_SEGM - 1), roff)];
                    o.z = lut[lut_word(v[k].z & (N_SEGM - 1), roff)];
                    o.w = lut[lut_word(v[k].w & (N_SEGM - 1), roff)];
                    __stcs(reinterpret_cast<float4*>(out) + i, o);
                }
            }
            #pragma unroll
            for (int k = 0; k < GPI; k++) v[k] = nv[k];
            base = next;
        }
    } else {
        // int64 path: each 4-pixel group = 32 B = two uint4 streaming loads.
        const uint4* sp = (const uint4*)segm;
        int base = blockIdx.x * THREADS * GPI + threadIdx.x;

        uint4 va[GPI], vb[GPI];
        #pragma unroll
        for (int k = 0; k < GPI; k++) {
            int i = base + k * THREADS;
            if (i < n4) {
                va[k] = __ldcs(sp + 2 * i);
                vb[k] = __ldcs(sp + 2 * i + 1);
            }
        }

        while (base < n4) {
            int next = base + stride;
            uint4 na[GPI], nb[GPI];
            #pragma unroll
            for (int k = 0; k < GPI; k++) {
                int i = next + k * THREADS;
                if (i < n4) {
                    na[k] = __ldcs(sp + 2 * i);
                    nb[k] = __ldcs(sp + 2 * i + 1);
                }
            }
            #pragma unroll
            for (int k = 0; k < GPI; k++) {
                int i = base + k * THREADS;
                if (i < n4) {
                    float4 o;   // low words of the 4 little-endian int64s
                    o.x = lut[lut_word((int)va[k].x & (N_SEGM - 1), roff)];
                    o.y = lut[lut_word((int)va[k].z & (N_SEGM - 1), roff)];
                    o.z = lut[lut_word((int)vb[k].x & (N_SEGM - 1), roff)];
                    o.w = lut[lut_word((int)vb[k].z & (N_SEGM - 1), roff)];
                    __stcs(reinterpret_cast<float4*>(out) + i, o);
                }
            }
            #pragma unroll
            for (int k = 0; k < GPI; k++) { va[k] = na[k]; vb[k] = nb[k]; }
            base = next;
        }
    }
}

// Scalar tail (only if out_size % 4 != 0; never for 4096*4096).
__global__ void superpixel2pixel_tail(const float* __restrict__ lut_g,
                                      const void*  __restrict__ segm,
                                      float*       __restrict__ out,
                                      int start, int n)
{
    __shared__ unsigned int probe_acc;
    if (threadIdx.x == 0) probe_acc = 0u;
    __syncthreads();
    if (threadIdx.x < 64) {
        uint4 w = reinterpret_cast<const uint4*>(segm)[threadIdx.x];
        unsigned int v = w.y | w.w;
        if (v) atomicOr(&probe_acc, v);
    }
    __syncthreads();
    const bool is64 = (probe_acc == 0u);

    int i = start + blockIdx.x * blockDim.x + threadIdx.x;
    if (i >= n) return;
    int idx;
    if (is64) idx = (int)reinterpret_cast<const long long*>(segm)[i];
    else      idx = reinterpret_cast<const int*>(segm)[i];
    out[i] = lut_g[idx & (N_SEGM - 1)];
}

extern "C" void kernel_launch(void* const* d_in, const int* in_sizes, int n_in,
                              void* d_out, int out_size)
{
    // Identify inputs by element count (LUT = 1024, index image = 16.7M).
    int lut_idx = 0, seg_idx = 1;
    if (n_in >= 2 && in_sizes[0] > in_sizes[1]) { lut_idx = 1; seg_idx = 0; }

    const float* lut  = (const float*)d_in[lut_idx];
    const void*  segm = d_in[seg_idx];
    float*       out  = (float*)d_out;

    int n  = out_size;
    int n4 = n >> 2;
    if (n4 > 0) {
        int blocks = (n4 + THREADS * GPI - 1) / (THREADS * GPI);
        if (blocks > MAX_BLOCKS) blocks = MAX_BLOCKS;
        superpixel2pixel_kernel<<<blocks, THREADS>>>(lut, segm, out, n4);
    }
    int rem_start = n4 << 2;
    if (n - rem_start > 0) {
        superpixel2pixel_tail<<<1, 256>>>(lut, segm, out, rem_start, n);
    }
}

// round 15
// speedup vs baseline: 1.0972x; 1.0972x over previous
#include <cuda_runtime.h>
#include <cuda_bf16.h>

// out[i] = input[segm_img[i]] : 1024-entry fp32 LUT gather over a 4096x4096
// index image. DRAM floor: 64MB idx read + 64MB out write ~= 19.7us @6.5TB/s.
//
// R9 (21.1us main, occ 94%, L1 59%): L1tex wavefronts dominated by 32->32-bank
// conflicted LDS. R12 (8-way sliced, 32KB, occ-6): conflicts fixed but occ
// 61% -> REGRESSED to 25.6us. Lesson: residency > LDS-phase savings.
// This round: 4-way bank-sliced LUT (16KB) at the R9 operating point --
// launch_bounds(256,8) (regs capped 32), 8 CTAs/SM (129KB smem < 228KB).
// Replica r lives in banks 8r..8r+7; lane l uses replica (l>>3)&3. Conflicts:
// max-of-4x(8-into-8) ~2.6 phases vs 3.9 -> ~20% fewer L1tex wavefronts.
//
// Dtype probe (per-CTA, 1KB, L2-hot): int64 values in [0,1024) have all-zero
// odd 32-bit words; random int32 indices OR to nonzero w.p. 1 - 1024^-128.

#define N_SEGM  1024
#define THREADS 256
#define GPI     2                 // 16B-index groups per thread per iteration
#define MAX_BLOCKS 1184           // 148 SMs * 8 CTAs -> one wave
#define LUT_WORDS (N_SEGM * 4)    // 4 replicas, bank-sliced, 16 KB

// word offset of LUT entry idx within a replica-adjusted base pointer
__device__ __forceinline__ int lut4(int idx) {
    return ((idx >> 3) << 5) | (idx & 7);
}

__global__ __launch_bounds__(THREADS, 8)
void superpixel2pixel_kernel(const float* __restrict__ lut_g,
                             const void*  __restrict__ segm,
                             float*       __restrict__ out,
                             int n4)   // number of 4-pixel groups
{
    __shared__ float lut[LUT_WORDS];
    __shared__ unsigned int probe_acc;

    if (threadIdx.x == 0) probe_acc = 0u;
    __syncthreads();

    if (threadIdx.x < 64) {
        uint4 w = reinterpret_cast<const uint4*>(segm)[threadIdx.x];
        unsigned int v = w.y | w.w;            // odd 32-bit words
        if (v) atomicOr(&probe_acc, v);
    }
    // Bank-sliced replicated LUT init: slot s -> replica=(s>>3)&3, row=s>>5,
    // col=s&7, entry = ((s>>5)<<3) | (s&7). 4096 words, source is L1/L2-hot.
    for (int s = threadIdx.x; s < LUT_WORDS; s += THREADS)
        lut[s] = lut_g[((s >> 5) << 3) | (s & 7)];
    __syncthreads();

    const bool   is64   = (probe_acc == 0u);   // uniform
    const int    stride = gridDim.x * THREADS * GPI;
    const float* myLut  = lut + (threadIdx.x & 24);  // lane's replica base

    if (!is64) {
        const int4* sp = (const int4*)segm;
        int base = blockIdx.x * THREADS * GPI + threadIdx.x;

        // prologue: prefetch iteration 0
        int4 v[GPI];
        #pragma unroll
        for (int k = 0; k < GPI; k++) {
            int i = base + k * THREADS;
            if (i < n4) v[k] = __ldcs(sp + i);
        }

        while (base < n4) {
            int next = base + stride;
            int4 nv[GPI];
            #pragma unroll
            for (int k = 0; k < GPI; k++) {
                int i = next + k * THREADS;
                if (i < n4) nv[k] = __ldcs(sp + i);
            }
            #pragma unroll
            for (int k = 0; k < GPI; k++) {
                int i = base + k * THREADS;
                if (i < n4) {
                    float4 o;
                    o.x = myLut[lut4(v[k].x & (N_SEGM - 1))];
                    o.y = myLut[lut4(v[k].y & (N_SEGM - 1))];
                    o.z = myLut[lut4(v[k].z & (N_SEGM - 1))];
                    o.w = myLut[lut4(v[k].w & (N_SEGM - 1))];
                    __stcs(reinterpret_cast<float4*>(out) + i, o);
                }
            }
            #pragma unroll
            for (int k = 0; k < GPI; k++) v[k] = nv[k];
            base = next;
        }
    } else {
        // int64 path: each 4-pixel group = 32 B = two uint4 streaming loads.
        const uint4* sp = (const uint4*)segm;
        int base = blockIdx.x * THREADS * GPI + threadIdx.x;

        uint4 va[GPI], vb[GPI];
        #pragma unroll
        for (int k = 0; k < GPI; k++) {
            int i = base + k * THREADS;
            if (i < n4) {
                va[k] = __ldcs(sp + 2 * i);
                vb[k] = __ldcs(sp + 2 * i + 1);
            }
        }

        while (base < n4) {
            int next = base + stride;
            uint4 na[GPI], nb[GPI];
            #pragma unroll
            for (int k = 0; k < GPI; k++) {
                int i = next + k * THREADS;
                if (i < n4) {
                    na[k] = __ldcs(sp + 2 * i);
                    nb[k] = __ldcs(sp + 2 * i + 1);
                }
            }
            #pragma unroll
            for (int k = 0; k < GPI; k++) {
                int i = base + k * THREADS;
                if (i < n4) {
                    float4 o;   // low words of the 4 little-endian int64s
                    o.x = myLut[lut4((int)va[k].x & (N_SEGM - 1))];
                    o.y = myLut[lut4((int)va[k].z & (N_SEGM - 1))];
                    o.z = myLut[lut4((int)vb[k].x & (N_SEGM - 1))];
                    o.w = myLut[lut4((int)vb[k].z & (N_SEGM - 1))];
                    __stcs(reinterpret_cast<float4*>(out) + i, o);
                }
            }
            #pragma unroll
            for (int k = 0; k < GPI; k++) { va[k] = na[k]; vb[k] = nb[k]; }
            base = next;
        }
    }
}

// Scalar tail (only if out_size % 4 != 0; never for 4096*4096).
__global__ void superpixel2pixel_tail(const float* __restrict__ lut_g,
                                      const void*  __restrict__ segm,
                                      float*       __restrict__ out,
                                      int start, int n)
{
    __shared__ unsigned int probe_acc;
    if (threadIdx.x == 0) probe_acc = 0u;
    __syncthreads();
    if (threadIdx.x < 64) {
        uint4 w = reinterpret_cast<const uint4*>(segm)[threadIdx.x];
        unsigned int v = w.y | w.w;
        if (v) atomicOr(&probe_acc, v);
    }
    __syncthreads();
    const bool is64 = (probe_acc == 0u);

    int i = start + blockIdx.x * blockDim.x + threadIdx.x;
    if (i >= n) return;
    int idx;
    if (is64) idx = (int)reinterpret_cast<const long long*>(segm)[i];
    else      idx = reinterpret_cast<const int*>(segm)[i];
    out[i] = lut_g[idx & (N_SEGM - 1)];
}

extern "C" void kernel_launch(void* const* d_in, const int* in_sizes, int n_in,
                              void* d_out, int out_size)
{
    // Identify inputs by element count (LUT = 1024, index image = 16.7M).
    int lut_idx = 0, seg_idx = 1;
    if (n_in >= 2 && in_sizes[0] > in_sizes[1]) { lut_idx = 1; seg_idx = 0; }

    const float* lut  = (const float*)d_in[lut_idx];
    const void*  segm = d_in[seg_idx];
    float*       out  = (float*)d_out;

    int n  = out_size;
    int n4 = n >> 2;
    if (n4 > 0) {
        int blocks = (n4 + THREADS * GPI - 1) / (THREADS * GPI);
        if (blocks > MAX_BLOCKS) blocks = MAX_BLOCKS;
        superpixel2pixel_kernel<<<blocks, THREADS>>>(lut, segm, out, n4);
    }
    int rem_start = n4 << 2;
    if (n - rem_start > 0) {
        superpixel2pixel_tail<<<1, 256>>>(lut, segm, out, rem_start, n);
    }
}

// round 16
// speedup vs baseline: 1.1743x; 1.0702x over previous
#include <cuda_runtime.h>
#include <cuda_bf16.h>

// out[i] = input[segm_img[i]] : 1024-entry fp32 LUT gather over a 4096x4096
// index image. DRAM floor: 64MB idx read + 64MB out write ~= 19.7us @6.5TB/s.
//
// History: R9 (plain smem LUT, persistent+prefetch) = 21.1us main / 24.5 total,
// occ 94%, DRAM 48.7%. R12 (8-way sliced LUT) and R15 (4-way sliced) BOTH
// regressed (25.6 / 25.1us) with DRAM *dropping* -> bank conflicts were never
// binding; the added address-ALU on the critical issue path was the cost.
// This round: R9 structure exactly, minus per-access bounds predicates:
// iters = n4/stride unguarded iterations + guarded epilogue. 1024 CTAs so
// n4=2^22 divides exactly (8 iters, empty epilogue).
//
// Dtype probe (per-CTA, 1KB, L2-hot): int64 values in [0,1024) have all-zero
// odd 32-bit words; random int32 indices OR to nonzero w.p. 1 - 1024^-128.

#define N_SEGM  1024
#define THREADS 256
#define GPI     2                 // 16B-index groups per thread per iteration
#define MAX_BLOCKS 1024           // <= 1 wave (148*8); 2^10 so 2^22 % stride == 0

__global__ __launch_bounds__(THREADS, 8)
void superpixel2pixel_kernel(const float* __restrict__ lut_g,
                             const void*  __restrict__ segm,
                             float*       __restrict__ out,
                             int n4)   // number of 4-pixel groups
{
    __shared__ float lut[N_SEGM];
    __shared__ unsigned int probe_acc;

    if (threadIdx.x == 0) probe_acc = 0u;
    __syncthreads();

    if (threadIdx.x < 64) {
        uint4 w = reinterpret_cast<const uint4*>(segm)[threadIdx.x];
        unsigned int v = w.y | w.w;            // odd 32-bit words
        if (v) atomicOr(&probe_acc, v);
    }
    for (int i = threadIdx.x; i < N_SEGM; i += THREADS)
        lut[i] = lut_g[i];
    __syncthreads();

    const bool is64   = (probe_acc == 0u);     // uniform
    const int  stride = gridDim.x * THREADS * GPI;
    const int  iters  = n4 / stride;           // fully-unguarded iterations

    if (!is64) {
        const int4* sp = (const int4*)segm;
        int base = blockIdx.x * THREADS * GPI + threadIdx.x;

        int4 v[GPI], nv[GPI];
        if (iters > 0) {
            // prologue: iteration 0 (unguarded)
            #pragma unroll
            for (int k = 0; k < GPI; k++)
                v[k] = __ldcs(sp + base + k * THREADS);

            for (int t = 1; t < iters; t++) {
                int nxt = base + stride;
                #pragma unroll
                for (int k = 0; k < GPI; k++)      // prefetch t (unguarded)
                    nv[k] = __ldcs(sp + nxt + k * THREADS);
                #pragma unroll
                for (int k = 0; k < GPI; k++) {    // process t-1
                    float4 o;
                    o.x = lut[v[k].x & (N_SEGM - 1)];
                    o.y = lut[v[k].y & (N_SEGM - 1)];
                    o.z = lut[v[k].z & (N_SEGM - 1)];
                    o.w = lut[v[k].w & (N_SEGM - 1)];
                    __stcs(reinterpret_cast<float4*>(out) + base + k * THREADS, o);
                }
                #pragma unroll
                for (int k = 0; k < GPI; k++) v[k] = nv[k];
                base = nxt;
            }
            // last full iteration: prefetch remainder (guarded), process last
            int rem = base + stride;
            #pragma unroll
            for (int k = 0; k < GPI; k++) {
                int i = rem + k * THREADS;
                if (i < n4) nv[k] = __ldcs(sp + i);
            }
            #pragma unroll
            for (int k = 0; k < GPI; k++) {
                float4 o;
                o.x = lut[v[k].x & (N_SEGM - 1)];
                o.y = lut[v[k].y & (N_SEGM - 1)];
                o.z = lut[v[k].z & (N_SEGM - 1)];
                o.w = lut[v[k].w & (N_SEGM - 1)];
                __stcs(reinterpret_cast<float4*>(out) + base + k * THREADS, o);
            }
            base = rem;
            #pragma unroll
            for (int k = 0; k < GPI; k++) v[k] = nv[k];
        }
        // guarded epilogue (empty when stride divides n4)
        #pragma unroll
        for (int k = 0; k < GPI; k++) {
            int i = base + k * THREADS;
            if (i < n4) {
                int4 w = (iters > 0) ? v[k] : __ldcs(sp + i);
                float4 o;
                o.x = lut[w.x & (N_SEGM - 1)];
                o.y = lut[w.y & (N_SEGM - 1)];
                o.z = lut[w.z & (N_SEGM - 1)];
                o.w = lut[w.w & (N_SEGM - 1)];
                __stcs(reinterpret_cast<float4*>(out) + i, o);
            }
        }
    } else {
        // int64 path (never taken for this dataset): simple guarded loop.
        const uint4* sp = (const uint4*)segm;
        for (int base = blockIdx.x * THREADS * GPI + threadIdx.x;
             base < n4; base += stride) {
            #pragma unroll
            for (int k = 0; k < GPI; k++) {
                int i = base + k * THREADS;
                if (i < n4) {
                    uint4 a = __ldcs(sp + 2 * i);
                    uint4 b = __ldcs(sp + 2 * i + 1);
                    float4 o;   // low words of the 4 little-endian int64s
                    o.x = lut[(int)a.x & (N_SEGM - 1)];
                    o.y = lut[(int)a.z & (N_SEGM - 1)];
                    o.z = lut[(int)b.x & (N_SEGM - 1)];
                    o.w = lut[(int)b.z & (N_SEGM - 1)];
                    __stcs(reinterpret_cast<float4*>(out) + i, o);
                }
            }
        }
    }
}

// Scalar tail (only if out_size % 4 != 0; never for 4096*4096).
__global__ void superpixel2pixel_tail(const float* __restrict__ lut_g,
                                      const void*  __restrict__ segm,
                                      float*       __restrict__ out,
                                      int start, int n)
{
    __shared__ unsigned int probe_acc;
    if (threadIdx.x == 0) probe_acc = 0u;
    __syncthreads();
    if (threadIdx.x < 64) {
        uint4 w = reinterpret_cast<const uint4*>(segm)[threadIdx.x];
        unsigned int v = w.y | w.w;
        if (v) atomicOr(&probe_acc, v);
    }
    __syncthreads();
    const bool is64 = (probe_acc == 0u);

    int i = start + blockIdx.x * blockDim.x + threadIdx.x;
    if (i >= n) return;
    int idx;
    if (is64) idx = (int)reinterpret_cast<const long long*>(segm)[i];
    else      idx = reinterpret_cast<const int*>(segm)[i];
    out[i] = lut_g[idx & (N_SEGM - 1)];
}

extern "C" void kernel_launch(void* const* d_in, const int* in_sizes, int n_in,
                              void* d_out, int out_size)
{
    // Identify inputs by element count (LUT = 1024, index image = 16.7M).
    int lut_idx = 0, seg_idx = 1;
    if (n_in >= 2 && in_sizes[0] > in_sizes[1]) { lut_idx = 1; seg_idx = 0; }

    const float* lut  = (const float*)d_in[lut_idx];
    const void*  segm = d_in[seg_idx];
    float*       out  = (float*)d_out;

    int n  = out_size;
    int n4 = n >> 2;
    if (n4 > 0) {
        int blocks = (n4 + THREADS * GPI - 1) / (THREADS * GPI);
        if (blocks > MAX_BLOCKS) blocks = MAX_BLOCKS;
        superpixel2pixel_kernel<<<blocks, THREADS>>>(lut, segm, out, n4);
    }
    int rem_start = n4 << 2;
    if (n - rem_start > 0) {
        superpixel2pixel_tail<<<1, 256>>>(lut, segm, out, rem_start, n);
    }
}

// round 17
// speedup vs baseline: 1.1758x; 1.0013x over previous
#include <cuda_runtime.h>
#include <cuda_bf16.h>

// out[i] = input[segm_img[i]] : 1024-entry fp32 LUT gather over a 4096x4096
// index image. Steady-state DRAM traffic per replay: 64MB idx read + 64MB
// output writeback = 128MB -> ~19.7us floor @6.5TB/s.
//
// Session evidence: dur tracks occupancy (94%->21.1us, 76.5%->22.3us,
// 61%->25.6us); LDS-conflict fixes and predicate stripping are second-order.
// This round combines the two proven wins: FULL 1184-CTA residency (R9) +
// unguarded inner loop (R16). iters = n4/stride = 6 unguarded prefetch
// iterations; only the final partial iteration carries bounds predicates.
//
// Dtype probe (per-CTA, 1KB, L2-hot): int64 values in [0,1024) have all-zero
// odd 32-bit words; random int32 indices OR to nonzero w.p. 1 - 1024^-128.

#define N_SEGM  1024
#define THREADS 256
#define GPI     2                 // 16B-index groups per thread per iteration
#define MAX_BLOCKS 1184           // 148 SMs * 8 CTAs -> one full wave

__global__ __launch_bounds__(THREADS, 8)
void superpixel2pixel_kernel(const float* __restrict__ lut_g,
                             const void*  __restrict__ segm,
                             float*       __restrict__ out,
                             int n4)   // number of 4-pixel groups
{
    __shared__ float lut[N_SEGM];
    __shared__ unsigned int probe_acc;

    if (threadIdx.x == 0) probe_acc = 0u;
    __syncthreads();

    if (threadIdx.x < 64) {
        uint4 w = reinterpret_cast<const uint4*>(segm)[threadIdx.x];
        unsigned int v = w.y | w.w;            // odd 32-bit words
        if (v) atomicOr(&probe_acc, v);
    }
    for (int i = threadIdx.x; i < N_SEGM; i += THREADS)
        lut[i] = lut_g[i];
    __syncthreads();

    const bool is64   = (probe_acc == 0u);     // uniform
    const int  stride = gridDim.x * THREADS * GPI;
    const int  iters  = n4 / stride;           // fully-unguarded iterations

    if (!is64) {
        const int4* sp = (const int4*)segm;
        int base = blockIdx.x * THREADS * GPI + threadIdx.x;

        int4 v[GPI], nv[GPI];
        if (iters > 0) {
            // prologue: iteration 0 (unguarded)
            #pragma unroll
            for (int k = 0; k < GPI; k++)
                v[k] = __ldcs(sp + base + k * THREADS);

            for (int t = 1; t < iters; t++) {
                int nxt = base + stride;
                #pragma unroll
                for (int k = 0; k < GPI; k++)      // prefetch t (unguarded)
                    nv[k] = __ldcs(sp + nxt + k * THREADS);
                #pragma unroll
                for (int k = 0; k < GPI; k++) {    // process t-1
                    float4 o;
                    o.x = lut[v[k].x & (N_SEGM - 1)];
                    o.y = lut[v[k].y & (N_SEGM - 1)];
                    o.z = lut[v[k].z & (N_SEGM - 1)];
                    o.w = lut[v[k].w & (N_SEGM - 1)];
                    __stcs(reinterpret_cast<float4*>(out) + base + k * THREADS, o);
                }
                #pragma unroll
                for (int k = 0; k < GPI; k++) v[k] = nv[k];
                base = nxt;
            }
            // last full iteration: prefetch remainder (guarded), process last
            int rem = base + stride;
            #pragma unroll
            for (int k = 0; k < GPI; k++) {
                int i = rem + k * THREADS;
                if (i < n4) nv[k] = __ldcs(sp + i);
            }
            #pragma unroll
            for (int k = 0; k < GPI; k++) {
                float4 o;
                o.x = lut[v[k].x & (N_SEGM - 1)];
                o.y = lut[v[k].y & (N_SEGM - 1)];
                o.z = lut[v[k].z & (N_SEGM - 1)];
                o.w = lut[v[k].w & (N_SEGM - 1)];
                __stcs(reinterpret_cast<float4*>(out) + base + k * THREADS, o);
            }
            base = rem;
            #pragma unroll
            for (int k = 0; k < GPI; k++) v[k] = nv[k];
        }
        // guarded remainder (one partial iteration when stride !| n4)
        #pragma unroll
        for (int k = 0; k < GPI; k++) {
            int i = base + k * THREADS;
            if (i < n4) {
                int4 w = (iters > 0) ? v[k] : __ldcs(sp + i);
                float4 o;
                o.x = lut[w.x & (N_SEGM - 1)];
                o.y = lut[w.y & (N_SEGM - 1)];
                o.z = lut[w.z & (N_SEGM - 1)];
                o.w = lut[w.w & (N_SEGM - 1)];
                __stcs(reinterpret_cast<float4*>(out) + i, o);
            }
        }
    } else {
        // int64 path (never taken for this dataset): simple guarded loop.
        const uint4* sp = (const uint4*)segm;
        for (int base = blockIdx.x * THREADS * GPI + threadIdx.x;
             base < n4; base += stride) {
            #pragma unroll
            for (int k = 0; k < GPI; k++) {
                int i = base + k * THREADS;
                if (i < n4) {
                    uint4 a = __ldcs(sp + 2 * i);
                    uint4 b = __ldcs(sp + 2 * i + 1);
                    float4 o;   // low words of the 4 little-endian int64s
                    o.x = lut[(int)a.x & (N_SEGM - 1)];
                    o.y = lut[(int)a.z & (N_SEGM - 1)];
                    o.z = lut[(int)b.x & (N_SEGM - 1)];
                    o.w = lut[(int)b.z & (N_SEGM - 1)];
                    __stcs(reinterpret_cast<float4*>(out) + i, o);
                }
            }
        }
    }
}

// Scalar tail (only if out_size % 4 != 0; never for 4096*4096).
__global__ void superpixel2pixel_tail(const float* __restrict__ lut_g,
                                      const void*  __restrict__ segm,
                                      float*       __restrict__ out,
                                      int start, int n)
{
    __shared__ unsigned int probe_acc;
    if (threadIdx.x == 0) probe_acc = 0u;
    __syncthreads();
    if (threadIdx.x < 64) {
        uint4 w = reinterpret_cast<const uint4*>(segm)[threadIdx.x];
        unsigned int v = w.y | w.w;
        if (v) atomicOr(&probe_acc, v);
    }
    __syncthreads();
    const bool is64 = (probe_acc == 0u);

    int i = start + blockIdx.x * blockDim.x + threadIdx.x;
    if (i >= n) return;
    int idx;
    if (is64) idx = (int)reinterpret_cast<const long long*>(segm)[i];
    else      idx = reinterpret_cast<const int*>(segm)[i];
    out[i] = lut_g[idx & (N_SEGM - 1)];
}

extern "C" void kernel_launch(void* const* d_in, const int* in_sizes, int n_in,
                              void* d_out, int out_size)
{
    // Identify inputs by element count (LUT = 1024, index image = 16.7M).
    int lut_idx = 0, seg_idx = 1;
    if (n_in >= 2 && in_sizes[0] > in_sizes[1]) { lut_idx = 1; seg_idx = 0; }

    const float* lut  = (const float*)d_in[lut_idx];
    const void*  segm = d_in[seg_idx];
    float*       out  = (float*)d_out;

    int n  = out_size;
    int n4 = n >> 2;
    if (n4 > 0) {
        int blocks = (n4 + THREADS * GPI - 1) / (THREADS * GPI);
        if (blocks > MAX_BLOCKS) blocks = MAX_BLOCKS;
        superpixel2pixel_kernel<<<blocks, THREADS>>>(lut, segm, out, n4);
    }
    int rem_start = n4 << 2;
    if (n - rem_start > 0) {
        superpixel2pixel_tail<<<1, 256>>>(lut, segm, out, rem_start, n);
    }
}